// round 3
// baseline (speedup 1.0000x reference)
#include <cuda_runtime.h>
#include <cuda_bf16.h>
#include <math.h>

// ---------------------------------------------------------------------------
// Shapes (fixed): B=32, C=256, T=32, L=32, d=1024, K=8, G=4, D=32, H=128
// ---------------------------------------------------------------------------
#define Bn   32
#define Cn   256
#define Dn   1024
#define Kn   8
#define Hn   128
#define OC   128

// ---------------- scratch (device globals; no runtime alloc) ----------------
__device__ float g_inp  [Bn * Cn * Dn];
__device__ float g_slots[Bn * Kn * Dn];
__device__ float g_sln  [Bn * Kn * Dn];
__device__ float g_q    [Bn * Kn * Dn];
__device__ float g_qw   [Bn * Kn * Dn];
__device__ float g_qbk  [Bn * Kn];
__device__ float g_dots [Bn * Kn * Cn];
__device__ float g_attn [Bn * Kn * Cn];
__device__ float g_aw   [Bn * Kn * Dn];
__device__ float g_upd  [Bn * Kn * Dn];
__device__ float g_hid  [Bn * Kn * Hn];
__device__ float g_W2p  [OC * 2 * Cn];
__device__ float g_E    [Bn * OC * Cn];
__device__ float g_mean [OC];
__device__ float g_var  [OC];
__device__ float g_part [4 * 256 * 3072];      // split-K / dual partials (12.6MB)

// ---------------------------------------------------------------------------
__device__ __forceinline__ float warp_sum(float v) {
    #pragma unroll
    for (int o = 16; o; o >>= 1) v += __shfl_down_sync(0xFFFFFFFFu, v, o);
    return v;
}

__global__ void ln_rows_kernel(const float* __restrict__ x, const float* __restrict__ g,
                               const float* __restrict__ b, float* __restrict__ y)
{
    int row = blockIdx.x;
    const float* xr = x + (long long)row * Dn;
    int tid = threadIdx.x;
    float s = 0.f, ss = 0.f;
    for (int c = tid; c < Dn; c += 256) { float v = xr[c]; s += v; ss += v * v; }
    s = warp_sum(s); ss = warp_sum(ss);
    __shared__ float shs[8], shss[8];
    __shared__ float mean_s, rstd_s;
    int lane = tid & 31, w = tid >> 5;
    if (lane == 0) { shs[w] = s; shss[w] = ss; }
    __syncthreads();
    if (tid == 0) {
        float S = 0.f, SS = 0.f;
        #pragma unroll
        for (int i = 0; i < 8; i++) { S += shs[i]; SS += shss[i]; }
        float m = S * (1.f / Dn);
        float var = SS * (1.f / Dn) - m * m;
        mean_s = m;
        rstd_s = rsqrtf(var + 1e-5f);
    }
    __syncthreads();
    float m = mean_s, r = rstd_s;
    float* yr = y + (long long)row * Dn;
    for (int c = tid; c < Dn; c += 256) yr[c] = (xr[c] - m) * r * g[c] + b[c];
}

__global__ void init_slots_kernel(const float* __restrict__ noise, const float* __restrict__ mu,
                                  const float* __restrict__ logsig, float* __restrict__ slots)
{
    int idx = blockIdx.x * 256 + threadIdx.x;
    int dch = idx & (Dn - 1);
    slots[idx] = mu[dch] + __expf(logsig[dch]) * noise[idx];
}

// ---------------------------------------------------------------------------
// SGEMM v2: 64x128 tile, BK=16, 4x8 microtile, 256 threads, double-buffered,
// vectorized smem reads (LDS.128). M mult of 64, N mult of 128, K mult 16*KS.
// KS==1: epilogue bias/accum/act to C (batched via bz*strides, or dual via
//        A2/B2/C2 pointer swap on bz==1). KS>1: raw partials at C + ks*M*N.
// act: 0 none, 1 relu, 2 gelu(exact)
// ---------------------------------------------------------------------------
__global__ void __launch_bounds__(256, 2)
gemm2(const float* __restrict__ A, const float* __restrict__ B,
      const float* __restrict__ bias, float* __restrict__ C,
      int M, int N, int K, int KS, int mblocks,
      long long sA, long long sB, long long sC,
      int transB, int act, int accum,
      const float* __restrict__ A2, const float* __restrict__ B2,
      const float* __restrict__ bias2, float* __restrict__ C2)
{
    __shared__ __align__(16) float As[2][16][68];
    __shared__ __align__(16) float Bs[2][16][132];
    int bz = blockIdx.z;
    const float* bp = bias;
    if (A2) {
        if (bz) { A = A2; B = B2; bp = bias2; C = C2; }
    } else if (bz) {
        A += bz * sA; B += bz * sB; C += bz * sC;
    }
    int mb = blockIdx.y % mblocks;
    int ks = blockIdx.y / mblocks;
    int m0 = mb * 64, n0 = blockIdx.x * 128;
    int Kc = K / KS;
    int kbeg = ks * Kc;
    int nk = Kc >> 4;
    int tid = threadIdx.x, tx = tid & 15, ty = tid >> 4;

    // A load: one float4 per thread along K; store transposed
    int am = tid >> 2, akq = (tid & 3) * 4;
    const float* Ap = A + (long long)(m0 + am) * K + kbeg + akq;

    // B load pointers
    const float* Bp0;
    long long bstep;      // per-pass offset
    int bk0, bn0;         // NN store indices
    if (transB) {
        bn0 = tid >> 2;                       // n (pass adds 64)
        bk0 = (tid & 3) * 4;                  // k quad
        Bp0 = B + (long long)(n0 + bn0) * K + kbeg + bk0;
        bstep = 64LL * K;
    } else {
        bk0 = tid >> 5;                       // k row (pass adds 8)
        bn0 = (tid & 31) * 4;                 // n quad
        Bp0 = B + (long long)(kbeg + bk0) * N + n0 + bn0;
        bstep = 8LL * N;
    }

    float4 aq, bq0, bq1;
    // prologue loads (tile 0)
    aq = *(const float4*)Ap;
    if (transB) {
        bq0 = *(const float4*)Bp0;
        bq1 = *(const float4*)(Bp0 + bstep);
    } else {
        bq0 = *(const float4*)Bp0;
        bq1 = *(const float4*)(Bp0 + bstep);
    }
    As[0][akq + 0][am] = aq.x; As[0][akq + 1][am] = aq.y;
    As[0][akq + 2][am] = aq.z; As[0][akq + 3][am] = aq.w;
    if (transB) {
        Bs[0][bk0 + 0][bn0] = bq0.x; Bs[0][bk0 + 1][bn0] = bq0.y;
        Bs[0][bk0 + 2][bn0] = bq0.z; Bs[0][bk0 + 3][bn0] = bq0.w;
        Bs[0][bk0 + 0][bn0 + 64] = bq1.x; Bs[0][bk0 + 1][bn0 + 64] = bq1.y;
        Bs[0][bk0 + 2][bn0 + 64] = bq1.z; Bs[0][bk0 + 3][bn0 + 64] = bq1.w;
    } else {
        *(float4*)&Bs[0][bk0][bn0] = bq0;
        *(float4*)&Bs[0][bk0 + 8][bn0] = bq1;
    }
    __syncthreads();

    float acc[4][8] = {};
    int cur = 0;
    for (int t = 0; t < nk; t++) {
        bool more = (t + 1 < nk);
        if (more) {
            aq = *(const float4*)(Ap + (t + 1) * 16);
            if (transB) {
                bq0 = *(const float4*)(Bp0 + (t + 1) * 16);
                bq1 = *(const float4*)(Bp0 + bstep + (t + 1) * 16);
            } else {
                bq0 = *(const float4*)(Bp0 + (long long)(t + 1) * 16 * N);
                bq1 = *(const float4*)(Bp0 + (long long)(t + 1) * 16 * N + bstep);
            }
        }
        #pragma unroll
        for (int kk = 0; kk < 16; kk++) {
            float4 av  = *(const float4*)&As[cur][kk][ty * 4];
            float4 bva = *(const float4*)&Bs[cur][kk][tx * 8];
            float4 bvb = *(const float4*)&Bs[cur][kk][tx * 8 + 4];
            float a[4] = {av.x, av.y, av.z, av.w};
            float b8[8] = {bva.x, bva.y, bva.z, bva.w, bvb.x, bvb.y, bvb.z, bvb.w};
            #pragma unroll
            for (int i = 0; i < 4; i++)
                #pragma unroll
                for (int j = 0; j < 8; j++)
                    acc[i][j] += a[i] * b8[j];
        }
        if (more) {
            int nb = cur ^ 1;
            As[nb][akq + 0][am] = aq.x; As[nb][akq + 1][am] = aq.y;
            As[nb][akq + 2][am] = aq.z; As[nb][akq + 3][am] = aq.w;
            if (transB) {
                Bs[nb][bk0 + 0][bn0] = bq0.x; Bs[nb][bk0 + 1][bn0] = bq0.y;
                Bs[nb][bk0 + 2][bn0] = bq0.z; Bs[nb][bk0 + 3][bn0] = bq0.w;
                Bs[nb][bk0 + 0][bn0 + 64] = bq1.x; Bs[nb][bk0 + 1][bn0 + 64] = bq1.y;
                Bs[nb][bk0 + 2][bn0 + 64] = bq1.z; Bs[nb][bk0 + 3][bn0 + 64] = bq1.w;
            } else {
                *(float4*)&Bs[nb][bk0][bn0] = bq0;
                *(float4*)&Bs[nb][bk0 + 8][bn0] = bq1;
            }
        }
        __syncthreads();
        cur ^= 1;
    }

    if (KS == 1) {
        #pragma unroll
        for (int i = 0; i < 4; i++) {
            int m = m0 + ty * 4 + i;
            float* Cr = C + (long long)m * N + n0 + tx * 8;
            float4 v0 = make_float4(acc[i][0], acc[i][1], acc[i][2], acc[i][3]);
            float4 v1 = make_float4(acc[i][4], acc[i][5], acc[i][6], acc[i][7]);
            if (bp) {
                const float* br = bp + n0 + tx * 8;
                v0.x += br[0]; v0.y += br[1]; v0.z += br[2]; v0.w += br[3];
                v1.x += br[4]; v1.y += br[5]; v1.z += br[6]; v1.w += br[7];
            }
            if (accum) {
                float4 c0 = *(float4*)Cr, c1 = *(float4*)(Cr + 4);
                v0.x += c0.x; v0.y += c0.y; v0.z += c0.z; v0.w += c0.w;
                v1.x += c1.x; v1.y += c1.y; v1.z += c1.z; v1.w += c1.w;
            }
            if (act == 1) {
                v0.x = fmaxf(v0.x, 0.f); v0.y = fmaxf(v0.y, 0.f);
                v0.z = fmaxf(v0.z, 0.f); v0.w = fmaxf(v0.w, 0.f);
                v1.x = fmaxf(v1.x, 0.f); v1.y = fmaxf(v1.y, 0.f);
                v1.z = fmaxf(v1.z, 0.f); v1.w = fmaxf(v1.w, 0.f);
            } else if (act == 2) {
                const float r2 = 0.70710678118654752f;
                v0.x = 0.5f * v0.x * (1.f + erff(v0.x * r2));
                v0.y = 0.5f * v0.y * (1.f + erff(v0.y * r2));
                v0.z = 0.5f * v0.z * (1.f + erff(v0.z * r2));
                v0.w = 0.5f * v0.w * (1.f + erff(v0.w * r2));
                v1.x = 0.5f * v1.x * (1.f + erff(v1.x * r2));
                v1.y = 0.5f * v1.y * (1.f + erff(v1.y * r2));
                v1.z = 0.5f * v1.z * (1.f + erff(v1.z * r2));
                v1.w = 0.5f * v1.w * (1.f + erff(v1.w * r2));
            }
            *(float4*)Cr = v0;
            *(float4*)(Cr + 4) = v1;
        }
    } else {
        float* Pr = C + (long long)ks * M * N;
        #pragma unroll
        for (int i = 0; i < 4; i++) {
            int m = m0 + ty * 4 + i;
            float* p = Pr + (long long)m * N + n0 + tx * 8;
            *(float4*)p = make_float4(acc[i][0], acc[i][1], acc[i][2], acc[i][3]);
            *(float4*)(p + 4) = make_float4(acc[i][4], acc[i][5], acc[i][6], acc[i][7]);
        }
    }
}

// combine split-K partials: C = act(sum_ks P + bias [+ C])
__global__ void combine_kernel(const float* __restrict__ P, const float* __restrict__ bias,
                               float* __restrict__ C, int MN, int N, int KS,
                               int act, int accum)
{
    int idx = blockIdx.x * 256 + threadIdx.x;
    float s = 0.f;
    for (int ks = 0; ks < KS; ks++) s += P[(long long)ks * MN + idx];
    if (bias) s += bias[idx % N];
    if (accum) s += C[idx];
    if (act == 1) s = fmaxf(s, 0.f);
    C[idx] = s;
}

__global__ void rowdot_kernel(const float* __restrict__ A, const float* __restrict__ v,
                              float* __restrict__ out)
{
    int row = blockIdx.x;
    float s = 0.f;
    for (int c = threadIdx.x; c < Dn; c += 32) s += A[(long long)row * Dn + c] * v[c];
    s = warp_sum(s);
    if (threadIdx.x == 0) out[row] = s;
}

__global__ void dots_kernel(const float* __restrict__ qw, const float* __restrict__ inp,
                            const float* __restrict__ qbk, float* __restrict__ dots)
{
    int j = blockIdx.x, b = blockIdx.y;
    int tid = threadIdx.x;
    const float* ir = inp + ((long long)b * Cn + j) * Dn;
    const float* qb = qw + (long long)b * Kn * Dn;
    float acc[Kn] = {};
    for (int e = tid; e < Dn; e += 256) {
        float xv = ir[e];
        #pragma unroll
        for (int i = 0; i < Kn; i++) acc[i] += xv * qb[i * Dn + e];
    }
    __shared__ float sh[Kn][9];
    int lane = tid & 31, w = tid >> 5;
    #pragma unroll
    for (int i = 0; i < Kn; i++) {
        float s = warp_sum(acc[i]);
        if (lane == 0) sh[i][w] = s;
    }
    __syncthreads();
    if (tid < Kn) {
        float s = 0.f;
        #pragma unroll
        for (int w2 = 0; w2 < 8; w2++) s += sh[tid][w2];
        dots[((long long)b * Kn + tid) * Cn + j] = (s + qbk[b * Kn + tid]) * 0.03125f;
    }
}

__global__ void softmax_slots_kernel(const float* __restrict__ dots, float* __restrict__ attn)
{
    int idx = blockIdx.x * 256 + threadIdx.x;
    int b = idx >> 8, j = idx & 255;
    const float* dp = dots + (long long)b * Kn * Cn + j;
    float v[Kn], mx = -1e30f;
    #pragma unroll
    for (int i = 0; i < Kn; i++) { v[i] = dp[i * Cn]; mx = fmaxf(mx, v[i]); }
    float s = 0.f;
    #pragma unroll
    for (int i = 0; i < Kn; i++) { v[i] = __expf(v[i] - mx); s += v[i]; }
    float inv = 1.f / s;
    float* ap = attn + (long long)b * Kn * Cn + j;
    #pragma unroll
    for (int i = 0; i < Kn; i++) ap[i * Cn] = v[i] * inv + 1e-8f;
}

__global__ void rownorm_kernel(float* __restrict__ attn, float eps)
{
    int row = blockIdx.x;
    int tid = threadIdx.x;
    float v = attn[row * Cn + tid];
    float s = warp_sum(v);
    __shared__ float sh[8];
    __shared__ float total;
    int lane = tid & 31, w = tid >> 5;
    if (lane == 0) sh[w] = s;
    __syncthreads();
    if (tid == 0) {
        float S = 0.f;
        #pragma unroll
        for (int i = 0; i < 8; i++) S += sh[i];
        total = S + eps;
    }
    __syncthreads();
    attn[row * Cn + tid] = v / total;
}

__global__ void aw_kernel(const float* __restrict__ attn, const float* __restrict__ inp,
                          float* __restrict__ aw)
{
    int row = blockIdx.x;
    int b = row >> 3;
    int tid = threadIdx.x;
    __shared__ float a_s[Cn];
    a_s[tid] = attn[row * Cn + tid];
    __syncthreads();
    float a0 = 0.f, a1 = 0.f, a2 = 0.f, a3 = 0.f;
    const float* xb = inp + (long long)b * Cn * Dn;
    #pragma unroll 4
    for (int j = 0; j < Cn; j++) {
        float aj = a_s[j];
        const float* r = xb + (long long)j * Dn + tid;
        a0 += aj * r[0];
        a1 += aj * r[256];
        a2 += aj * r[512];
        a3 += aj * r[768];
    }
    float* o = aw + (long long)row * Dn + tid;
    o[0] = a0; o[256] = a1; o[512] = a2; o[768] = a3;
}

// GRU gate fusion reading split-K partials (KS=2) + biases directly
__global__ void gru_kernel(const float* __restrict__ Pi, const float* __restrict__ Ph,
                           const float* __restrict__ b_ih, const float* __restrict__ b_hh,
                           float* __restrict__ slots)
{
    const int MN = 256 * 3072;
    int idx = blockIdx.x * 256 + threadIdx.x;   // < 262144
    int r = idx >> 10, c = idx & (Dn - 1);
    long long base = (long long)r * 3 * Dn + c;
    float ir = Pi[base] + Pi[MN + base] + b_ih[c];
    float iz = Pi[base + Dn] + Pi[MN + base + Dn] + b_ih[c + Dn];
    float ic = Pi[base + 2 * Dn] + Pi[MN + base + 2 * Dn] + b_ih[c + 2 * Dn];
    float hr = Ph[base] + Ph[MN + base] + b_hh[c];
    float hz = Ph[base + Dn] + Ph[MN + base + Dn] + b_hh[c + Dn];
    float hc = Ph[base + 2 * Dn] + Ph[MN + base + 2 * Dn] + b_hh[c + 2 * Dn];
    float rg   = 1.f / (1.f + __expf(-(ir + hr)));
    float z    = 1.f / (1.f + __expf(-(iz + hz)));
    float cand = tanhf(ic + rg * hc);
    float h = slots[idx];
    slots[idx] = (1.f - z) * cand + z * h;
}

__global__ void w2p_kernel(const float* __restrict__ Wbr, const float* __restrict__ Wp,
                           float* __restrict__ W2p)
{
    int o = blockIdx.x;
    int tid = threadIdx.x;
    __shared__ float wr[64];
    if (tid < 64) wr[tid] = Wbr[o * 64 + tid];
    __syncthreads();
    #pragma unroll
    for (int w = 0; w < 2; w++) {
        int idx = tid + w * 256;
        int j = idx >> 8, c = idx & 255;
        float s = 0.f;
        #pragma unroll
        for (int dp = 0; dp < 32; dp++) s += wr[j * 32 + dp] * Wp[dp * Cn + c];
        W2p[o * 512 + idx] = s;
    }
}

__global__ void e_kernel(const float* __restrict__ attn, const float* __restrict__ W2p,
                         const float* __restrict__ gates, float* __restrict__ E)
{
    int idx = blockIdx.x * 256 + threadIdx.x;
    int c = idx & 255, o = (idx >> 8) & 127, b = idx >> 15;
    int g = o >> 5;
    float s = 0.f;
    #pragma unroll
    for (int j = 0; j < 2; j++) {
        int k = g * 2 + j;
        float gt = fmaxf(gates[k], 0.f);
        s += gt * attn[((long long)b * Kn + k) * Cn + c] * W2p[o * 512 + j * 256 + c];
    }
    E[idx] = s;
}

__global__ void bn_stats_kernel(const float* __restrict__ y, float* __restrict__ mean,
                                float* __restrict__ var)
{
    int o = blockIdx.x;
    int tid = threadIdx.x;
    float s = 0.f, ss = 0.f;
    for (int b = 0; b < Bn; b++) {
        const float* r = y + (long long)b * OC * Dn + (long long)o * Dn;
        for (int t = tid; t < Dn; t += 256) { float v = r[t]; s += v; ss += v * v; }
    }
    s = warp_sum(s); ss = warp_sum(ss);
    __shared__ float shs[8], shss[8];
    int lane = tid & 31, w = tid >> 5;
    if (lane == 0) { shs[w] = s; shss[w] = ss; }
    __syncthreads();
    if (tid == 0) {
        float S = 0.f, SS = 0.f;
        #pragma unroll
        for (int i = 0; i < 8; i++) { S += shs[i]; SS += shss[i]; }
        float m = S / (float)(Bn * Dn);
        mean[o] = m;
        var[o] = SS / (float)(Bn * Dn) - m * m;
    }
}

__global__ void bn_apply_kernel(float* __restrict__ y, const float* __restrict__ mean,
                                const float* __restrict__ var, const float* __restrict__ bg,
                                const float* __restrict__ bb)
{
    int idx = blockIdx.x * 256 + threadIdx.x;
    int o = (idx >> 10) & 127;
    float v = y[idx];
    y[idx] = (v - mean[o]) * rsqrtf(var[o] + 1e-5f) * bg[o] + bb[o];
}

// ---------------------------------------------------------------------------
extern "C" void kernel_launch(void* const* d_in, const int* in_sizes, int n_in,
                              void* d_out, int out_size)
{
    const float* x       = (const float*)d_in[0];
    const float* noise   = (const float*)d_in[1];
    const float* mu      = (const float*)d_in[2];
    const float* logsig  = (const float*)d_in[3];
    const float* Wq      = (const float*)d_in[4];
    const float* bq      = (const float*)d_in[5];
    const float* Wk      = (const float*)d_in[6];
    const float* bk      = (const float*)d_in[7];
    const float* Wv      = (const float*)d_in[8];
    const float* bv      = (const float*)d_in[9];
    const float* W_ih    = (const float*)d_in[10];
    const float* b_ih    = (const float*)d_in[11];
    const float* W_hh    = (const float*)d_in[12];
    const float* b_hh    = (const float*)d_in[13];
    const float* W1      = (const float*)d_in[14];
    const float* b1      = (const float*)d_in[15];
    const float* W2      = (const float*)d_in[16];
    const float* b2      = (const float*)d_in[17];
    const float* ln_in_g = (const float*)d_in[18];
    const float* ln_in_b = (const float*)d_in[19];
    const float* ln_s_g  = (const float*)d_in[20];
    const float* ln_s_b  = (const float*)d_in[21];
    const float* ln_ff_g = (const float*)d_in[22];
    const float* ln_ff_b = (const float*)d_in[23];
    const float* Wp      = (const float*)d_in[24];
    const float* gates   = (const float*)d_in[25];
    const float* Wbr     = (const float*)d_in[26];
    const float* bn_g    = (const float*)d_in[27];
    const float* bn_b    = (const float*)d_in[28];
    float* out = (float*)d_out;

    float *inp, *slots, *sln, *q, *qw, *qbk, *dots, *attn, *aw, *upd,
          *hid, *W2p, *E, *mean, *var, *part;
    cudaGetSymbolAddress((void**)&inp,   g_inp);
    cudaGetSymbolAddress((void**)&slots, g_slots);
    cudaGetSymbolAddress((void**)&sln,   g_sln);
    cudaGetSymbolAddress((void**)&q,     g_q);
    cudaGetSymbolAddress((void**)&qw,    g_qw);
    cudaGetSymbolAddress((void**)&qbk,   g_qbk);
    cudaGetSymbolAddress((void**)&dots,  g_dots);
    cudaGetSymbolAddress((void**)&attn,  g_attn);
    cudaGetSymbolAddress((void**)&aw,    g_aw);
    cudaGetSymbolAddress((void**)&upd,   g_upd);
    cudaGetSymbolAddress((void**)&hid,   g_hid);
    cudaGetSymbolAddress((void**)&W2p,   g_W2p);
    cudaGetSymbolAddress((void**)&E,     g_E);
    cudaGetSymbolAddress((void**)&mean,  g_mean);
    cudaGetSymbolAddress((void**)&var,   g_var);
    cudaGetSymbolAddress((void**)&part,  g_part);

    const int M = Bn * Kn;          // 256
    float* partB = part + 2 * 256 * 3072;   // second half for GRU z=1

    ln_rows_kernel<<<Bn * Cn, 256>>>(x, ln_in_g, ln_in_b, inp);
    init_slots_kernel<<<(Bn * Kn * Dn) / 256, 256>>>(noise, mu, logsig, slots);

    for (int it = 0; it < 3; it++) {
        // q = LN_s(slots) @ Wq^T + bq   (KS=8 -> 256 blocks)
        ln_rows_kernel<<<M, 256>>>(slots, ln_s_g, ln_s_b, sln);
        gemm2<<<dim3(8, 32), 256>>>(sln, Wq, nullptr, part, M, Dn, Dn, 8, 4,
                                    0, 0, 0, 1, 0, 0, nullptr, nullptr, nullptr, nullptr);
        combine_kernel<<<(M * Dn) / 256, 256>>>(part, bq, q, M * Dn, Dn, 8, 0, 0);
        // qw = q @ Wk (NN, KS=8)
        gemm2<<<dim3(8, 32), 256>>>(q, Wk, nullptr, part, M, Dn, Dn, 8, 4,
                                    0, 0, 0, 0, 0, 0, nullptr, nullptr, nullptr, nullptr);
        combine_kernel<<<(M * Dn) / 256, 256>>>(part, nullptr, qw, M * Dn, Dn, 8, 0, 0);
        rowdot_kernel<<<M, 32>>>(q, bk, qbk);
        // attention
        dots_kernel<<<dim3(Cn, Bn), 256>>>(qw, inp, qbk, dots);
        softmax_slots_kernel<<<(Bn * Cn) / 256, 256>>>(dots, attn);
        rownorm_kernel<<<M, Cn>>>(attn, 0.f);
        // upd = (attn @ inp) @ Wv^T + bv   (KS=8)
        aw_kernel<<<M, 256>>>(attn, inp, aw);
        gemm2<<<dim3(8, 32), 256>>>(aw, Wv, nullptr, part, M, Dn, Dn, 8, 4,
                                    0, 0, 0, 1, 0, 0, nullptr, nullptr, nullptr, nullptr);
        combine_kernel<<<(M * Dn) / 256, 256>>>(part, bv, upd, M * Dn, Dn, 8, 0, 0);
        // GRU: dual GEMM (gi/gh) KS=2 -> 384 blocks; partials consumed by gru_kernel
        gemm2<<<dim3(24, 8, 2), 256>>>(upd, W_ih, nullptr, part, M, 3 * Dn, Dn, 2, 4,
                                       0, 0, 0, 1, 0, 0, slots, W_hh, nullptr, partB);
        gru_kernel<<<(M * Dn) / 256, 256>>>(part, partB, b_ih, b_hh, slots);
        // MLP residual
        ln_rows_kernel<<<M, 256>>>(slots, ln_ff_g, ln_ff_b, sln);
        gemm2<<<dim3(1, 32), 256>>>(sln, W1, nullptr, part, M, Hn, Dn, 8, 4,
                                    0, 0, 0, 1, 0, 0, nullptr, nullptr, nullptr, nullptr);
        combine_kernel<<<(M * Hn) / 256, 256>>>(part, b1, hid, M * Hn, Hn, 8, 1, 0);
        gemm2<<<dim3(8, 8), 256>>>(hid, W2, nullptr, part, M, Dn, Hn, 2, 4,
                                   0, 0, 0, 1, 0, 0, nullptr, nullptr, nullptr, nullptr);
        combine_kernel<<<(M * Dn) / 256, 256>>>(part, b2, slots, M * Dn, Dn, 2, 0, 1);
    }

    rownorm_kernel<<<M, Cn>>>(attn, 1e-9f);

    // fused router + branch: out = gelu(E @ x) per batch, 512 blocks
    w2p_kernel<<<OC, 256>>>(Wbr, Wp, W2p);
    e_kernel<<<(Bn * OC * Cn) / 256, 256>>>(attn, W2p, gates, E);
    gemm2<<<dim3(8, 2, Bn), 256>>>(E, x, nullptr, out, OC, Dn, Cn, 1, 2,
                                   (long long)OC * Cn, (long long)Cn * Dn,
                                   (long long)OC * Dn, 0, 2, 0,
                                   nullptr, nullptr, nullptr, nullptr);

    bn_stats_kernel<<<OC, 256>>>(out, mean, var);
    bn_apply_kernel<<<(Bn * OC * Dn) / 256, 256>>>(out, mean, var, bn_g, bn_b);
}